// round 15
// baseline (speedup 1.0000x reference)
#include <cuda_runtime.h>
#include <cuda_bf16.h>
#include <cstdint>

#define B_  8
#define C_  256
#define L_  2048

// ---------------------------------------------------------------------------
// Scratch (no cudaMalloc allowed)
// ---------------------------------------------------------------------------
__device__ __align__(16) __nv_bfloat16 g_xT[B_ * L_ * C_];   // [B,L,C]
__device__ __align__(16) __nv_bfloat16 g_Wb[3 * C_ * C_];    // q,k,v weights
__device__ __align__(16) __nv_bfloat16 g_qT[B_ * L_ * C_];   // [B,L,C]
__device__ __align__(16) __nv_bfloat16 g_kT[B_ * L_ * C_];   // [B,L,C]
__device__ __align__(16) __nv_bfloat16 g_v [B_ * C_ * L_];   // [B,C,L]

// ---------------------------------------------------------------------------
// common helpers
// ---------------------------------------------------------------------------
__device__ __forceinline__ uint32_t smem_u32(const void* p) {
    uint32_t a;
    asm("{ .reg .u64 t; cvta.to.shared.u64 t, %1; cvt.u32.u64 %0, t; }" : "=r"(a) : "l"(p));
    return a;
}
#define CP16(dst, src) \
    asm volatile("cp.async.cg.shared.global [%0], [%1], 16;" :: "r"(dst), "l"(src))
#define CP_COMMIT() asm volatile("cp.async.commit_group;" ::: "memory")
#define CP_WAIT0()  asm volatile("cp.async.wait_group 0;" ::: "memory")
#define CP_WAIT1()  asm volatile("cp.async.wait_group 1;" ::: "memory")

__device__ __forceinline__ void mma_bf16(float acc[4], const uint32_t a[4],
                                         const uint32_t b[2]) {
    asm volatile(
        "mma.sync.aligned.m16n8k16.row.col.f32.bf16.bf16.f32 "
        "{%0,%1,%2,%3}, {%4,%5,%6,%7}, {%8,%9}, {%0,%1,%2,%3};"
        : "+f"(acc[0]), "+f"(acc[1]), "+f"(acc[2]), "+f"(acc[3])
        : "r"(a[0]), "r"(a[1]), "r"(a[2]), "r"(a[3]), "r"(b[0]), "r"(b[1]));
}
__device__ __forceinline__ void ldsm_x4(uint32_t addr, uint32_t r[4]) {
    asm volatile("ldmatrix.sync.aligned.m8n8.x4.shared.b16 {%0,%1,%2,%3}, [%4];"
        : "=r"(r[0]), "=r"(r[1]), "=r"(r[2]), "=r"(r[3]) : "r"(addr));
}

extern __shared__ __align__(16) char dynsmem[];

// ===========================================================================
//  FUSED ATTENTION v3 — 2 CTAs/SM. grid (L/64, B), 128 threads = 4 warps.
//  Warp: 16 rows x 128 keys (S, register P), 16 rows x 256 ch (O).
//  K: 2 x 64c-chunk buffers. V: 2 x 32-key buffers (80 B rows).
// ===========================================================================
#define FT_NTHR 128
#define QROW 528                       // 256 bf16 + 16B pad
#define KROW 144                       // 64 bf16 + 16B pad
#define VROW 80                        // 32 bf16 + 16B pad (bank-perm verified)
#define OFF_Q   0                      // 64 x 528    = 33792
#define OFF_K   33792                  // 2 x 128x144 = 36864
#define KBUFSZ  18432
#define OFF_V   70656                  // 2 x 256x80  = 40960
#define VBUFSZ  20480
#define FT_SMEM 111616                 // x2 CTAs = 223232 <= 228KB

__device__ __forceinline__ void ft_load_Q(const __nv_bfloat16* q, int tid, uint32_t sb) {
#pragma unroll
    for (int it = 0; it < 16; it++) {
        int s = tid + it * FT_NTHR;       // 0..2047
        int row = s >> 5, u = s & 31;
        CP16(sb + OFF_Q + row * QROW + u * 16, q + (size_t)row * C_ + u * 8);
    }
}
__device__ __forceinline__ void ft_load_K(const __nv_bfloat16* k, int key0, int cchunk,
                                          int buf, int tid, uint32_t sb) {
#pragma unroll
    for (int it = 0; it < 8; it++) {
        int s = tid + it * FT_NTHR;       // 0..1023
        int row = s >> 3, u = s & 7;
        CP16(sb + OFF_K + buf * KBUFSZ + row * KROW + u * 16,
             k + (size_t)(key0 + row) * C_ + cchunk * 64 + u * 8);
    }
}
// 32-key V window starting at absolute key index kb, all 256 channels
__device__ __forceinline__ void ft_load_V(const __nv_bfloat16* v, int kb,
                                          int buf, int tid, uint32_t sb) {
#pragma unroll
    for (int it = 0; it < 8; it++) {
        int s = tid + it * FT_NTHR;       // 0..1023
        int ch = s >> 2, seg = s & 3;
        CP16(sb + OFF_V + buf * VBUFSZ + ch * VROW + seg * 16,
             v + (size_t)ch * L_ + kb + seg * 8);
    }
}

__global__ __launch_bounds__(FT_NTHR, 2)
void flash_kernel(const float* __restrict__ x, float* __restrict__ out)
{
    const int tid = threadIdx.x, wid = tid >> 5, lane = tid & 31;
    const int l0 = blockIdx.x * 64, b = blockIdx.y;
    const uint32_t sb = smem_u32(dynsmem);

    const __nv_bfloat16* qg = g_qT + (size_t)b * L_ * C_ + (size_t)l0 * C_;
    const __nv_bfloat16* kg = g_kT + (size_t)b * L_ * C_;
    const __nv_bfloat16* vg = g_v + (size_t)b * C_ * L_;

    float acc_o[32][4];                  // 16 rows x 256 ch per warp
#pragma unroll
    for (int nt = 0; nt < 32; nt++)
#pragma unroll
        for (int j = 0; j < 4; j++) acc_o[nt][j] = 0.0f;
    float l_lo = 0.0f, l_hi = 0.0f;

    const uint32_t q_base = sb + OFF_Q
        + (uint32_t)(wid * 16 + (lane & 15)) * QROW + (lane >> 4) * 16;
    const uint32_t kb_off = (uint32_t)((lane & 7) + ((lane >> 4) & 1) * 8) * KROW
                            + ((lane >> 3) & 1) * 16;
    const uint32_t vb_off = (uint32_t)((lane & 7) + ((lane >> 4) & 1) * 8) * VROW
                            + ((lane >> 3) & 1) * 16;

    const float scale2 = 0.0625f * 1.4426950408889634f;  // 256^-0.5 * log2(e)

    // warmup groups: [Q],[c0->buf0],[c1->buf1]   (pending = 3)
    ft_load_Q(qg, tid, sb);               CP_COMMIT();
    ft_load_K(kg, 0, 0, 0, tid, sb);      CP_COMMIT();
    ft_load_K(kg, 0, 1, 1, tid, sb);      CP_COMMIT();

    for (int kt = 0; kt < 16; kt++) {
        const int key0 = kt * 128;

        float acc_s[16][4];
#pragma unroll
        for (int nt = 0; nt < 16; nt++)
#pragma unroll
            for (int j = 0; j < 4; j++) acc_s[nt][j] = 0.0f;

        // ---- S phase: 4 c-chunks; chunk cc in buf cc&1 ----
        // FIFO audit (steady): enter [c1']; cc0 W1 noop; cc1 W0 drain c1';
        // commit c2->buf0 (cc0 reads fenced by cc1 sync); cc2 W0 (c2);
        // commit c3->buf1 (cc1 fenced); cc3 W0 (c3); commit V0->VA,V1->VB.
#pragma unroll
        for (int cc = 0; cc < 4; cc++) {
            if (cc == 0)      { CP_WAIT1(); __syncthreads(); }
            else if (cc == 1) { CP_WAIT0(); __syncthreads();
                                ft_load_K(kg, key0, 2, 0, tid, sb); CP_COMMIT(); }
            else if (cc == 2) { CP_WAIT0(); __syncthreads();
                                ft_load_K(kg, key0, 3, 1, tid, sb); CP_COMMIT(); }
            else              { CP_WAIT0(); __syncthreads();
                                ft_load_V(vg, key0,      0, tid, sb); CP_COMMIT();
                                ft_load_V(vg, key0 + 32, 1, tid, sb); CP_COMMIT(); }
            const uint32_t kbuf = sb + OFF_K + (cc & 1) * KBUFSZ + kb_off;
            uint32_t aa[2][4];
            ldsm_x4(q_base + cc * 128, aa[0]);
#pragma unroll
            for (int ks = 0; ks < 4; ks++) {
                if (ks < 3)
                    ldsm_x4(q_base + cc * 128 + (ks + 1) * 32, aa[(ks + 1) & 1]);
                uint32_t bb[2][4];
                ldsm_x4(kbuf + ks * 32, bb[0]);
#pragma unroll
                for (int np = 0; np < 8; np++) {
                    if (np < 7)
                        ldsm_x4(kbuf + (np + 1) * (16 * KROW) + ks * 32, bb[(np + 1) & 1]);
                    mma_bf16(acc_s[2 * np],     aa[ks & 1], &bb[np & 1][0]);
                    mma_bf16(acc_s[2 * np + 1], aa[ks & 1], &bb[np & 1][2]);
                }
            }
        }

        // ---- softmax hoisted: P into registers, warp-local l sums ----
        uint32_t pr[8][4];
#pragma unroll
        for (int j = 0; j < 8; j++) {
            float p00 = exp2f(acc_s[2 * j][0] * scale2);
            float p01 = exp2f(acc_s[2 * j][1] * scale2);
            float p02 = exp2f(acc_s[2 * j][2] * scale2);
            float p03 = exp2f(acc_s[2 * j][3] * scale2);
            float p10 = exp2f(acc_s[2 * j + 1][0] * scale2);
            float p11 = exp2f(acc_s[2 * j + 1][1] * scale2);
            float p12 = exp2f(acc_s[2 * j + 1][2] * scale2);
            float p13 = exp2f(acc_s[2 * j + 1][3] * scale2);
            l_lo += p00 + p01 + p10 + p11;
            l_hi += p02 + p03 + p12 + p13;
            *(__nv_bfloat162*)&pr[j][0] = __floats2bfloat162_rn(p00, p01);
            *(__nv_bfloat162*)&pr[j][1] = __floats2bfloat162_rn(p02, p03);
            *(__nv_bfloat162*)&pr[j][2] = __floats2bfloat162_rn(p10, p11);
            *(__nv_bfloat162*)&pr[j][3] = __floats2bfloat162_rn(p12, p13);
        }

        // ---- O phase: 8 k-steps of 16 keys; V bufs alternate every 2 j ----
        // FIFO (steady): j0 W1 drain V0 (leave V1), commit c0'->buf0;
        // j2 W1 drain V1 (leave c0'), commit V2->VA; j4 W0 drain c0'+V2,
        // commit V3->VB + c1'->buf1; j6 W1 drain V3 (leave c1').
#pragma unroll
        for (int j = 0; j < 8; j++) {
            if (j == 0) {
                CP_WAIT1(); __syncthreads();
                if (kt + 1 < 16) {
                    ft_load_K(kg, key0 + 128, 0, 0, tid, sb); CP_COMMIT();
                }
            } else if (j == 2) {
                if (kt + 1 < 16) { CP_WAIT1(); } else { CP_WAIT0(); }
                __syncthreads();
                ft_load_V(vg, key0 + 64, 0, tid, sb); CP_COMMIT();
            } else if (j == 4) {
                CP_WAIT0(); __syncthreads();
                ft_load_V(vg, key0 + 96, 1, tid, sb); CP_COMMIT();
                if (kt + 1 < 16) {
                    ft_load_K(kg, key0 + 128, 1, 1, tid, sb); CP_COMMIT();
                }
            } else if (j == 6) {
                if (kt + 1 < 16) { CP_WAIT1(); } else { CP_WAIT0(); }
                __syncthreads();
            }
            const uint32_t vb = sb + OFF_V + ((j >> 1) & 1) * VBUFSZ + vb_off
                                + (j & 1) * 32;
            uint32_t bb[2][4];
            ldsm_x4(vb, bb[0]);
#pragma unroll
            for (int np = 0; np < 16; np++) {
                if (np < 15)
                    ldsm_x4(vb + (np + 1) * (16 * VROW), bb[(np + 1) & 1]);
                mma_bf16(acc_o[2 * np],     pr[j], &bb[np & 1][0]);
                mma_bf16(acc_o[2 * np + 1], pr[j], &bb[np & 1][2]);
            }
        }
        // tile exit pending: [c1'] — next cc0 W1 noop, cc1 W0 drains ✓
    }

    // ---- epilogue ----
    const int g = lane >> 2, tc = lane & 3;
    l_lo += __shfl_xor_sync(~0u, l_lo, 1);
    l_lo += __shfl_xor_sync(~0u, l_lo, 2);
    l_hi += __shfl_xor_sync(~0u, l_hi, 1);
    l_hi += __shfl_xor_sync(~0u, l_hi, 2);
    const float inv_lo = 1.0f / l_lo;
    const float inv_hi = 1.0f / l_hi;

    const int rlo = l0 + wid * 16 + g;
    const int rhi = rlo + 8;
    const float* xb = x + (size_t)b * C_ * L_;
    float* ob = out + (size_t)b * C_ * L_;
#pragma unroll
    for (int nt = 0; nt < 32; nt++) {
        const int ch = nt * 8 + 2 * tc;
        size_t i00 = (size_t)ch * L_ + rlo;
        size_t i10 = (size_t)(ch + 1) * L_ + rlo;
        size_t i02 = (size_t)ch * L_ + rhi;
        size_t i12 = (size_t)(ch + 1) * L_ + rhi;
        ob[i00] = acc_o[nt][0] * inv_lo + xb[i00];
        ob[i10] = acc_o[nt][1] * inv_lo + xb[i10];
        ob[i02] = acc_o[nt][2] * inv_hi + xb[i02];
        ob[i12] = acc_o[nt][3] * inv_hi + xb[i12];
    }
}

// ===========================================================================
//  QKV projection (unchanged, 256 threads, 2x4 warps)
// ===========================================================================
#define NTHR 256
#define ROWB 144
#define TILE_B (128 * ROWB)
#define STAGE  (2 * TILE_B)
#define NSTAGE 3
#define SMEM_DYN (NSTAGE * STAGE)

__device__ __forceinline__ void load_pair(int slot,
                                          const __nv_bfloat16* __restrict__ A, int lda,
                                          const __nv_bfloat16* __restrict__ Bt, int ldb,
                                          int tid, uint32_t sb) {
    const uint32_t base = sb + slot * STAGE;
#pragma unroll
    for (int it = 0; it < 4; it++) {
        int s = tid + it * NTHR;
        int row = s >> 3;
        int c4 = s & 7;
        CP16(base + row * ROWB + c4 * 16, A + (size_t)row * lda + c4 * 8);
        CP16(base + TILE_B + row * ROWB + c4 * 16, Bt + (size_t)row * ldb + c4 * 8);
    }
}

__device__ __forceinline__ void mma_chunk16(uint32_t As, uint32_t Bs,
                                            int wr, int wc, int lane,
                                            float acc[4][4][4]) {
    const uint32_t aoff = (uint32_t)(wr * 64 + (lane & 15)) * ROWB + (lane >> 4) * 16;
    const uint32_t boff = (uint32_t)(wc * 32 + (lane & 7) + ((lane >> 4) & 1) * 8) * ROWB
                          + ((lane >> 3) & 1) * 16;
#pragma unroll
    for (int ks = 0; ks < 4; ks++) {
        uint32_t a[4][4], b[2][4];
#pragma unroll
        for (int mt = 0; mt < 4; mt++)
            ldsm_x4(As + aoff + mt * (16 * ROWB) + ks * 32, a[mt]);
#pragma unroll
        for (int np = 0; np < 2; np++)
            ldsm_x4(Bs + boff + np * (16 * ROWB) + ks * 32, b[np]);
#pragma unroll
        for (int mt = 0; mt < 4; mt++)
#pragma unroll
            for (int nt = 0; nt < 4; nt++)
                mma_bf16(acc[mt][nt], a[mt], &b[nt >> 1][(nt & 1) * 2]);
    }
}

__device__ __forceinline__ void gemm128(const __nv_bfloat16* __restrict__ Ag, int lda,
                                        const __nv_bfloat16* __restrict__ Bg, int ldb,
                                        int KC, float acc[4][4][4]) {
    const int tid = threadIdx.x;
    const int wid = tid >> 5, lane = tid & 31;
    const int wr = wid >> 2, wc = wid & 3;
    const uint32_t sb = smem_u32(dynsmem);

    load_pair(0, Ag, lda, Bg, ldb, tid, sb);
    CP_COMMIT();
    load_pair(1, Ag + 64, lda, Bg + 64, ldb, tid, sb);
    CP_COMMIT();

    for (int kb = 0; kb < KC; kb++) {
        if (kb + 1 < KC) { CP_WAIT1(); } else { CP_WAIT0(); }
        __syncthreads();
        if (kb + 2 < KC) {
            load_pair((kb + 2) % NSTAGE, Ag + (size_t)(kb + 2) * 64, lda,
                      Bg + (size_t)(kb + 2) * 64, ldb, tid, sb);
            CP_COMMIT();
        }
        const uint32_t As = sb + (kb % NSTAGE) * STAGE;
        mma_chunk16(As, As + TILE_B, wr, wc, lane, acc);
        __syncthreads();
    }
}

#define ACC_INIT(acc) \
    do { \
        _Pragma("unroll") for (int i = 0; i < 4; i++) \
        _Pragma("unroll") for (int j = 0; j < 4; j++) \
        _Pragma("unroll") for (int q = 0; q < 4; q++) acc[i][j][q] = 0.0f; \
    } while (0)

// ---------------------------------------------------------------------------
// conv v2: z<8 -> xT transpose+convert; z==8 -> W convert.
// grid (16, 8, 9), block (32, 8)
// ---------------------------------------------------------------------------
__global__ void conv_kernel(const float* __restrict__ x,
                            const float* __restrict__ Wq,
                            const float* __restrict__ Wk,
                            const float* __restrict__ Wv) {
    const int tx = threadIdx.x, ty = threadIdx.y;
    const int tid = ty * 32 + tx;
    if (blockIdx.z == 8) {
        int gid = (blockIdx.y * 16 + blockIdx.x) * 256 + tid;   // 0..32767
#pragma unroll
        for (int r = 0; r < 2; r++) {
            int f = gid + r * 32768;
            if (f < 49152) {
                int p = f >> 14;
                int off = (f & 16383) * 4;
                const float* W = (p == 0) ? Wq : (p == 1) ? Wk : Wv;
                float4 w = *(const float4*)(W + off);
                __nv_bfloat16* o = g_Wb + p * C_ * C_ + off;
                *(__nv_bfloat162*)(o)     = __floats2bfloat162_rn(w.x, w.y);
                *(__nv_bfloat162*)(o + 2) = __floats2bfloat162_rn(w.z, w.w);
            }
        }
        return;
    }
    __shared__ float t[32][133];
    const int b = blockIdx.z, l0 = blockIdx.x * 128, c0 = blockIdx.y * 32;
    const float* xb = x + (size_t)b * C_ * L_;
#pragma unroll
    for (int i = ty; i < 32; i += 8) {
        float4 v = *(const float4*)(xb + (size_t)(c0 + i) * L_ + l0 + tx * 4);
        t[i][tx * 4 + 0] = v.x;
        t[i][tx * 4 + 1] = v.y;
        t[i][tx * 4 + 2] = v.z;
        t[i][tx * 4 + 3] = v.w;
    }
    __syncthreads();
    __nv_bfloat16* o = g_xT + (size_t)b * L_ * C_;
#pragma unroll
    for (int it = 0; it < 16; it++) {
        int j = it * 8 + ty;
        o[(size_t)(l0 + j) * C_ + c0 + tx] = __float2bfloat16_rn(t[tx][j]);
    }
}

__global__ __launch_bounds__(NTHR)
void qkv16_kernel(const float* __restrict__ bq,
                  const float* __restrict__ bk,
                  const float* __restrict__ bv)
{
    const int tid = threadIdx.x, wid = tid >> 5, lane = tid & 31;
    const int wr = wid >> 2, wc = wid & 3;
    const int z = blockIdx.z, b = z / 3, p = z - b * 3;
    const int l0 = blockIdx.x * 128, o0 = blockIdx.y * 128;
    const float* bias = (p == 0) ? bq : (p == 1) ? bk : bv;

    const __nv_bfloat16* Ag = g_Wb + p * C_ * C_ + (size_t)o0 * C_;
    const __nv_bfloat16* Bg = g_xT + (size_t)b * L_ * C_ + (size_t)l0 * C_;

    float acc[4][4][4];
    ACC_INIT(acc);
    gemm128(Ag, C_, Bg, C_, C_ / 64, acc);

    const int r = lane >> 2, c = lane & 3;
    if (p < 2) {
        __nv_bfloat16* oT = (p == 0 ? g_qT : g_kT) + (size_t)b * L_ * C_;
#pragma unroll
        for (int mt = 0; mt < 4; mt++) {
            int o = o0 + wr * 64 + mt * 16 + r;
            float bo = bias[o], bo8 = bias[o + 8];
#pragma unroll
            for (int nt = 0; nt < 4; nt++) {
                int l = l0 + wc * 32 + nt * 8 + 2 * c;
                oT[(size_t)l * C_ + o]           = __float2bfloat16_rn(acc[mt][nt][0] + bo);
                oT[(size_t)(l + 1) * C_ + o]     = __float2bfloat16_rn(acc[mt][nt][1] + bo);
                oT[(size_t)l * C_ + o + 8]       = __float2bfloat16_rn(acc[mt][nt][2] + bo8);
                oT[(size_t)(l + 1) * C_ + o + 8] = __float2bfloat16_rn(acc[mt][nt][3] + bo8);
            }
        }
    } else {
        __nv_bfloat16* ov = g_v + (size_t)b * C_ * L_;
#pragma unroll
        for (int mt = 0; mt < 4; mt++) {
            int o = o0 + wr * 64 + mt * 16 + r;
            float bo = bias[o], bo8 = bias[o + 8];
#pragma unroll
            for (int nt = 0; nt < 4; nt++) {
                int l = l0 + wc * 32 + nt * 8 + 2 * c;
                *(__nv_bfloat162*)(ov + (size_t)o * L_ + l) =
                    __floats2bfloat162_rn(acc[mt][nt][0] + bo, acc[mt][nt][1] + bo);
                *(__nv_bfloat162*)(ov + (size_t)(o + 8) * L_ + l) =
                    __floats2bfloat162_rn(acc[mt][nt][2] + bo8, acc[mt][nt][3] + bo8);
            }
        }
    }
}

// ---------------------------------------------------------------------------
// Launch
// ---------------------------------------------------------------------------
extern "C" void kernel_launch(void* const* d_in, const int* in_sizes, int n_in,
                              void* d_out, int out_size)
{
    (void)in_sizes; (void)n_in; (void)out_size;
    const float* x  = (const float*)d_in[0];
    const float* Wq = (const float*)d_in[1];
    const float* bq = (const float*)d_in[2];
    const float* Wk = (const float*)d_in[3];
    const float* bk = (const float*)d_in[4];
    const float* Wv = (const float*)d_in[5];
    const float* bv = (const float*)d_in[6];
    float* out = (float*)d_out;

    cudaFuncSetAttribute((const void*)qkv16_kernel,
                         cudaFuncAttributeMaxDynamicSharedMemorySize, SMEM_DYN);
    cudaFuncSetAttribute((const void*)flash_kernel,
                         cudaFuncAttributeMaxDynamicSharedMemorySize, FT_SMEM);

    dim3 gx(L_ / 128, C_ / 32, B_ + 1);     // (16, 8, 9): z==8 does W convert
    conv_kernel<<<gx, dim3(32, 8)>>>(x, Wq, Wk, Wv);

    dim3 gq(L_ / 128, C_ / 128, B_ * 3);    // (16, 2, 24)
    qkv16_kernel<<<gq, NTHR, SMEM_DYN>>>(bq, bk, bv);

    dim3 gf(L_ / 64, B_);                   // (32, 8) = 256 CTAs, 2/SM
    flash_kernel<<<gf, FT_NTHR, FT_SMEM>>>(x, out);
}

// round 16
// speedup vs baseline: 1.2279x; 1.2279x over previous
#include <cuda_runtime.h>
#include <cuda_bf16.h>
#include <cstdint>

#define B_  8
#define C_  256
#define L_  2048

// ---------------------------------------------------------------------------
// Scratch (no cudaMalloc allowed)
// ---------------------------------------------------------------------------
__device__ __align__(16) __nv_bfloat16 g_xT[B_ * L_ * C_];   // [B,L,C]
__device__ __align__(16) __nv_bfloat16 g_Wb[3 * C_ * C_];    // q,k,v weights
__device__ __align__(16) __nv_bfloat16 g_qT[B_ * L_ * C_];   // [B,L,C]
__device__ __align__(16) __nv_bfloat16 g_kT[B_ * L_ * C_];   // [B,L,C]
__device__ __align__(16) __nv_bfloat16 g_v [B_ * C_ * L_];   // [B,C,L]

// ---------------------------------------------------------------------------
// common helpers
// ---------------------------------------------------------------------------
__device__ __forceinline__ uint32_t smem_u32(const void* p) {
    uint32_t a;
    asm("{ .reg .u64 t; cvta.to.shared.u64 t, %1; cvt.u32.u64 %0, t; }" : "=r"(a) : "l"(p));
    return a;
}
#define CP16(dst, src) \
    asm volatile("cp.async.cg.shared.global [%0], [%1], 16;" :: "r"(dst), "l"(src))
#define CP_COMMIT() asm volatile("cp.async.commit_group;" ::: "memory")
#define CP_WAIT0()  asm volatile("cp.async.wait_group 0;" ::: "memory")
#define CP_WAIT1()  asm volatile("cp.async.wait_group 1;" ::: "memory")
#define CP_WAIT2()  asm volatile("cp.async.wait_group 2;" ::: "memory")
#define CP_WAIT3()  asm volatile("cp.async.wait_group 3;" ::: "memory")
#define CP_WAIT4()  asm volatile("cp.async.wait_group 4;" ::: "memory")

__device__ __forceinline__ void mma_bf16(float acc[4], const uint32_t a[4],
                                         const uint32_t b[2]) {
    asm volatile(
        "mma.sync.aligned.m16n8k16.row.col.f32.bf16.bf16.f32 "
        "{%0,%1,%2,%3}, {%4,%5,%6,%7}, {%8,%9}, {%0,%1,%2,%3};"
        : "+f"(acc[0]), "+f"(acc[1]), "+f"(acc[2]), "+f"(acc[3])
        : "r"(a[0]), "r"(a[1]), "r"(a[2]), "r"(a[3]), "r"(b[0]), "r"(b[1]));
}
__device__ __forceinline__ void ldsm_x4(uint32_t addr, uint32_t r[4]) {
    asm volatile("ldmatrix.sync.aligned.m8n8.x4.shared.b16 {%0,%1,%2,%3}, [%4];"
        : "=r"(r[0]), "=r"(r[1]), "=r"(r[2]), "=r"(r[3]) : "r"(addr));
}

extern __shared__ __align__(16) char dynsmem[];

// ===========================================================================
//  FUSED ATTENTION — register-resident P, 4-buffer K ring, 2 syncs/tile.
//  grid (L/128, B), 256 threads = 8 warps. Warp: 16 rows x 128 keys (S),
//  16 rows x 256 ch (O).  (R13 structure; epilogue staged through smem.)
// ===========================================================================
#define FT_NTHR 256
#define QROW 528                       // 256 bf16 + 16B pad
#define KROW 144                       // 64 bf16 + 16B pad
#define VROW 144
#define OFF_Q   0                      // 128 x 528   = 67584
#define OFF_K   67584                  // 4 x 128x144 = 73728
#define KBUFSZ  18432
#define OFF_V   141312                 // 2 x 256x144 = 73728
#define VBUFSZ  36864
#define FT_SMEM 215040
#define OROW 132                       // fp32 stage: 128 rows + 4 pad

__device__ __forceinline__ void ft_load_Q(const __nv_bfloat16* q, int tid, uint32_t sb) {
#pragma unroll
    for (int it = 0; it < 16; it++) {
        int s = tid + it * FT_NTHR;       // 0..4095
        int row = s >> 5, u = s & 31;
        CP16(sb + OFF_Q + row * QROW + u * 16, q + (size_t)row * C_ + u * 8);
    }
}
__device__ __forceinline__ void ft_load_K(const __nv_bfloat16* k, int key0, int cchunk,
                                          int tid, uint32_t sb) {
#pragma unroll
    for (int it = 0; it < 4; it++) {
        int s = tid + it * FT_NTHR;       // 0..1023
        int row = s >> 3, u = s & 7;
        CP16(sb + OFF_K + cchunk * KBUFSZ + row * KROW + u * 16,
             k + (size_t)(key0 + row) * C_ + cchunk * 64 + u * 8);
    }
}
// half h of the V tile: keys [key0 + h*64, +64), all 256 channels
__device__ __forceinline__ void ft_load_V(const __nv_bfloat16* v, int key0, int h,
                                          int tid, uint32_t sb) {
#pragma unroll
    for (int it = 0; it < 8; it++) {
        int s = tid + it * FT_NTHR;       // 0..2047
        int row = s >> 3, u = s & 7;      // row = channel
        CP16(sb + OFF_V + h * VBUFSZ + row * VROW + u * 16,
             v + (size_t)row * L_ + key0 + h * 64 + u * 8);
    }
}

__global__ __launch_bounds__(FT_NTHR, 1)
void flash_kernel(const float* __restrict__ x, float* __restrict__ out)
{
    const int tid = threadIdx.x, wid = tid >> 5, lane = tid & 31;
    const int l0 = blockIdx.x * 128, b = blockIdx.y;
    const uint32_t sb = smem_u32(dynsmem);

    const __nv_bfloat16* qg = g_qT + (size_t)b * L_ * C_ + (size_t)l0 * C_;
    const __nv_bfloat16* kg = g_kT + (size_t)b * L_ * C_;
    const __nv_bfloat16* vg = g_v + (size_t)b * C_ * L_;

    float acc_o[32][4];                  // 16 rows x 256 ch per warp
#pragma unroll
    for (int nt = 0; nt < 32; nt++)
#pragma unroll
        for (int j = 0; j < 4; j++) acc_o[nt][j] = 0.0f;
    float l_lo = 0.0f, l_hi = 0.0f;

    const uint32_t q_base = sb + OFF_Q
        + (uint32_t)(wid * 16 + (lane & 15)) * QROW + (lane >> 4) * 16;
    const uint32_t kb_off = (uint32_t)((lane & 7) + ((lane >> 4) & 1) * 8) * KROW
                            + ((lane >> 3) & 1) * 16;
    const uint32_t vb_off = (uint32_t)((lane & 7) + ((lane >> 4) & 1) * 8) * VROW
                            + ((lane >> 3) & 1) * 16;

    const float scale2 = 0.0625f * 1.4426950408889634f;  // 256^-0.5 * log2(e)

    // warmup: groups [Q],[c0],[c1]
    ft_load_Q(qg, tid, sb);            CP_COMMIT();
    ft_load_K(kg, 0, 0, tid, sb);      CP_COMMIT();
    ft_load_K(kg, 0, 1, tid, sb);      CP_COMMIT();

    for (int kt = 0; kt < 16; kt++) {
        const int key0 = kt * 128;

        float acc_s[16][4];
#pragma unroll
        for (int nt = 0; nt < 16; nt++)
#pragma unroll
            for (int j = 0; j < 4; j++) acc_s[nt][j] = 0.0f;

        // ---- S phase: chunk c lives in buffer c (no intra-tile reuse) ----
        // cc0: WAIT1 (c0 ready), SYNC (fences prev tile's V/K reads),
        //      then commit [c2],[c3],[V0],[V1].
        // cc1: WAIT4 (c1) | cc2: WAIT3 (c2) | cc3: WAIT2 (c3)   (no syncs)
#pragma unroll
        for (int cc = 0; cc < 4; cc++) {
            if (cc == 0) {
                CP_WAIT1();
                __syncthreads();
                ft_load_K(kg, key0, 2, tid, sb); CP_COMMIT();
                ft_load_K(kg, key0, 3, tid, sb); CP_COMMIT();
                ft_load_V(vg, key0, 0, tid, sb); CP_COMMIT();
                ft_load_V(vg, key0, 1, tid, sb); CP_COMMIT();
            }
            else if (cc == 1) { CP_WAIT4(); }
            else if (cc == 2) { CP_WAIT3(); }
            else              { CP_WAIT2(); }
            const uint32_t kbuf = sb + OFF_K + cc * KBUFSZ + kb_off;
#pragma unroll
            for (int ks = 0; ks < 4; ks++) {
                uint32_t a[4];
                ldsm_x4(q_base + cc * 128 + ks * 32, a);
                uint32_t bb[2][4];
                ldsm_x4(kbuf + ks * 32, bb[0]);
#pragma unroll
                for (int np = 0; np < 8; np++) {
                    if (np < 7)
                        ldsm_x4(kbuf + (np + 1) * (16 * KROW) + ks * 32, bb[(np + 1) & 1]);
                    mma_bf16(acc_s[2 * np],     a, &bb[np & 1][0]);
                    mma_bf16(acc_s[2 * np + 1], a, &bb[np & 1][2]);
                }
            }
        }

        // ---- O phase: exp2 + cvt (P in registers) fused with V MMAs ----
#pragma unroll
        for (int j = 0; j < 8; j++) {
            float p00 = exp2f(acc_s[2 * j][0] * scale2);
            float p01 = exp2f(acc_s[2 * j][1] * scale2);
            float p02 = exp2f(acc_s[2 * j][2] * scale2);
            float p03 = exp2f(acc_s[2 * j][3] * scale2);
            float p10 = exp2f(acc_s[2 * j + 1][0] * scale2);
            float p11 = exp2f(acc_s[2 * j + 1][1] * scale2);
            float p12 = exp2f(acc_s[2 * j + 1][2] * scale2);
            float p13 = exp2f(acc_s[2 * j + 1][3] * scale2);
            l_lo += p00 + p01 + p10 + p11;
            l_hi += p02 + p03 + p12 + p13;
            uint32_t a[4];
            *(__nv_bfloat162*)&a[0] = __floats2bfloat162_rn(p00, p01);
            *(__nv_bfloat162*)&a[1] = __floats2bfloat162_rn(p02, p03);
            *(__nv_bfloat162*)&a[2] = __floats2bfloat162_rn(p10, p11);
            *(__nv_bfloat162*)&a[3] = __floats2bfloat162_rn(p12, p13);

            if (j == 0) {
                CP_WAIT1();                    // V0 complete (V1 newest pending)
                __syncthreads();               // fences S-phase K reads
                if (kt + 1 < 16) {             // next tile's c0/c1 into bufs 0/1
                    ft_load_K(kg, key0 + 128, 0, tid, sb); CP_COMMIT();
                    ft_load_K(kg, key0 + 128, 1, tid, sb); CP_COMMIT();
                }
            } else if (j == 4) {
                if (kt + 1 < 16) { CP_WAIT2(); } else { CP_WAIT0(); }  // V1 done
            }

            const uint32_t vb = sb + OFF_V + (j >> 2) * VBUFSZ + vb_off + (j & 3) * 32;
            uint32_t bb[2][4];
            ldsm_x4(vb, bb[0]);
#pragma unroll
            for (int np = 0; np < 16; np++) {
                if (np < 15)
                    ldsm_x4(vb + (np + 1) * (16 * VROW), bb[(np + 1) & 1]);
                mma_bf16(acc_o[2 * np],     a, &bb[np & 1][0]);
                mma_bf16(acc_o[2 * np + 1], a, &bb[np & 1][2]);
            }
        }
        // next tile's cc0 sync fences this tile's V reads before V rewrites
    }

    // ---- epilogue: stage normalized O in smem [ch][row], coalesced out ----
    const int g = lane >> 2, tc = lane & 3;
    l_lo += __shfl_xor_sync(~0u, l_lo, 1);
    l_lo += __shfl_xor_sync(~0u, l_lo, 2);
    l_hi += __shfl_xor_sync(~0u, l_hi, 1);
    l_hi += __shfl_xor_sync(~0u, l_hi, 2);
    const float inv_lo = 1.0f / l_lo;
    const float inv_hi = 1.0f / l_hi;

    __syncthreads();   // all K/V/Q smem uses done; reuse as fp32 stage
    float* smemf = (float*)dynsmem;    // [256 ch][OROW]; 135168 B <= FT_SMEM
    const int rlo_l = wid * 16 + g;    // block-local rows
    const int rhi_l = rlo_l + 8;
#pragma unroll
    for (int nt = 0; nt < 32; nt++) {
        const int ch = nt * 8 + 2 * tc;
        // banks: (ch*OROW + row) mod 32 = (4*ch + row) mod 32 = 8tc+g distinct ✓
        smemf[ch * OROW + rlo_l]       = acc_o[nt][0] * inv_lo;
        smemf[(ch + 1) * OROW + rlo_l] = acc_o[nt][1] * inv_lo;
        smemf[ch * OROW + rhi_l]       = acc_o[nt][2] * inv_hi;
        smemf[(ch + 1) * OROW + rhi_l] = acc_o[nt][3] * inv_hi;
    }
    __syncthreads();

    const float* xb = x + (size_t)b * C_ * L_;
    float* ob = out + (size_t)b * C_ * L_;
    // 256 ch x 128 rows = 8192 float4, 32 per thread, fully coalesced
#pragma unroll
    for (int it = 0; it < 32; it++) {
        int gid = tid + it * FT_NTHR;     // 0..8191
        int ch = gid >> 5;                // 32 float4 per channel row
        int seg = gid & 31;
        size_t go = (size_t)ch * L_ + l0 + seg * 4;
        float4 xv = *(const float4*)(xb + go);
        const float* sp = smemf + ch * OROW + seg * 4;
        float4 o;
        o.x = sp[0] + xv.x;
        o.y = sp[1] + xv.y;
        o.z = sp[2] + xv.z;
        o.w = sp[3] + xv.w;
        *(float4*)(ob + go) = o;
    }
}

// ===========================================================================
//  QKV projection (unchanged, 256 threads, 2x4 warps)
// ===========================================================================
#define NTHR 256
#define ROWB 144
#define TILE_B (128 * ROWB)
#define STAGE  (2 * TILE_B)
#define NSTAGE 3
#define SMEM_DYN (NSTAGE * STAGE)

__device__ __forceinline__ void load_pair(int slot,
                                          const __nv_bfloat16* __restrict__ A, int lda,
                                          const __nv_bfloat16* __restrict__ Bt, int ldb,
                                          int tid, uint32_t sb) {
    const uint32_t base = sb + slot * STAGE;
#pragma unroll
    for (int it = 0; it < 4; it++) {
        int s = tid + it * NTHR;
        int row = s >> 3;
        int c4 = s & 7;
        CP16(base + row * ROWB + c4 * 16, A + (size_t)row * lda + c4 * 8);
        CP16(base + TILE_B + row * ROWB + c4 * 16, Bt + (size_t)row * ldb + c4 * 8);
    }
}

__device__ __forceinline__ void mma_chunk16(uint32_t As, uint32_t Bs,
                                            int wr, int wc, int lane,
                                            float acc[4][4][4]) {
    const uint32_t aoff = (uint32_t)(wr * 64 + (lane & 15)) * ROWB + (lane >> 4) * 16;
    const uint32_t boff = (uint32_t)(wc * 32 + (lane & 7) + ((lane >> 4) & 1) * 8) * ROWB
                          + ((lane >> 3) & 1) * 16;
#pragma unroll
    for (int ks = 0; ks < 4; ks++) {
        uint32_t a[4][4], b[2][4];
#pragma unroll
        for (int mt = 0; mt < 4; mt++)
            ldsm_x4(As + aoff + mt * (16 * ROWB) + ks * 32, a[mt]);
#pragma unroll
        for (int np = 0; np < 2; np++)
            ldsm_x4(Bs + boff + np * (16 * ROWB) + ks * 32, b[np]);
#pragma unroll
        for (int mt = 0; mt < 4; mt++)
#pragma unroll
            for (int nt = 0; nt < 4; nt++)
                mma_bf16(acc[mt][nt], a[mt], &b[nt >> 1][(nt & 1) * 2]);
    }
}

__device__ __forceinline__ void gemm128(const __nv_bfloat16* __restrict__ Ag, int lda,
                                        const __nv_bfloat16* __restrict__ Bg, int ldb,
                                        int KC, float acc[4][4][4]) {
    const int tid = threadIdx.x;
    const int wid = tid >> 5, lane = tid & 31;
    const int wr = wid >> 2, wc = wid & 3;
    const uint32_t sb = smem_u32(dynsmem);

    load_pair(0, Ag, lda, Bg, ldb, tid, sb);
    CP_COMMIT();
    load_pair(1, Ag + 64, lda, Bg + 64, ldb, tid, sb);
    CP_COMMIT();

    for (int kb = 0; kb < KC; kb++) {
        if (kb + 1 < KC) { CP_WAIT1(); } else { CP_WAIT0(); }
        __syncthreads();
        if (kb + 2 < KC) {
            load_pair((kb + 2) % NSTAGE, Ag + (size_t)(kb + 2) * 64, lda,
                      Bg + (size_t)(kb + 2) * 64, ldb, tid, sb);
            CP_COMMIT();
        }
        const uint32_t As = sb + (kb % NSTAGE) * STAGE;
        mma_chunk16(As, As + TILE_B, wr, wc, lane, acc);
        __syncthreads();
    }
}

#define ACC_INIT(acc) \
    do { \
        _Pragma("unroll") for (int i = 0; i < 4; i++) \
        _Pragma("unroll") for (int j = 0; j < 4; j++) \
        _Pragma("unroll") for (int q = 0; q < 4; q++) acc[i][j][q] = 0.0f; \
    } while (0)

// ---------------------------------------------------------------------------
// conv v2: z<8 -> xT transpose+convert; z==8 -> W convert.
// grid (16, 8, 9), block (32, 8)
// ---------------------------------------------------------------------------
__global__ void conv_kernel(const float* __restrict__ x,
                            const float* __restrict__ Wq,
                            const float* __restrict__ Wk,
                            const float* __restrict__ Wv) {
    const int tx = threadIdx.x, ty = threadIdx.y;
    const int tid = ty * 32 + tx;
    if (blockIdx.z == 8) {
        int gid = (blockIdx.y * 16 + blockIdx.x) * 256 + tid;   // 0..32767
#pragma unroll
        for (int r = 0; r < 2; r++) {
            int f = gid + r * 32768;
            if (f < 49152) {
                int p = f >> 14;
                int off = (f & 16383) * 4;
                const float* W = (p == 0) ? Wq : (p == 1) ? Wk : Wv;
                float4 w = *(const float4*)(W + off);
                __nv_bfloat16* o = g_Wb + p * C_ * C_ + off;
                *(__nv_bfloat162*)(o)     = __floats2bfloat162_rn(w.x, w.y);
                *(__nv_bfloat162*)(o + 2) = __floats2bfloat162_rn(w.z, w.w);
            }
        }
        return;
    }
    __shared__ float t[32][133];
    const int b = blockIdx.z, l0 = blockIdx.x * 128, c0 = blockIdx.y * 32;
    const float* xb = x + (size_t)b * C_ * L_;
#pragma unroll
    for (int i = ty; i < 32; i += 8) {
        float4 v = *(const float4*)(xb + (size_t)(c0 + i) * L_ + l0 + tx * 4);
        t[i][tx * 4 + 0] = v.x;
        t[i][tx * 4 + 1] = v.y;
        t[i][tx * 4 + 2] = v.z;
        t[i][tx * 4 + 3] = v.w;
    }
    __syncthreads();
    __nv_bfloat16* o = g_xT + (size_t)b * L_ * C_;
#pragma unroll
    for (int it = 0; it < 16; it++) {
        int j = it * 8 + ty;
        o[(size_t)(l0 + j) * C_ + c0 + tx] = __float2bfloat16_rn(t[tx][j]);
    }
}

__global__ __launch_bounds__(NTHR)
void qkv16_kernel(const float* __restrict__ bq,
                  const float* __restrict__ bk,
                  const float* __restrict__ bv)
{
    const int tid = threadIdx.x, wid = tid >> 5, lane = tid & 31;
    const int wr = wid >> 2, wc = wid & 3;
    const int z = blockIdx.z, b = z / 3, p = z - b * 3;
    const int l0 = blockIdx.x * 128, o0 = blockIdx.y * 128;
    const float* bias = (p == 0) ? bq : (p == 1) ? bk : bv;

    const __nv_bfloat16* Ag = g_Wb + p * C_ * C_ + (size_t)o0 * C_;
    const __nv_bfloat16* Bg = g_xT + (size_t)b * L_ * C_ + (size_t)l0 * C_;

    float acc[4][4][4];
    ACC_INIT(acc);
    gemm128(Ag, C_, Bg, C_, C_ / 64, acc);

    const int r = lane >> 2, c = lane & 3;
    if (p < 2) {
        __nv_bfloat16* oT = (p == 0 ? g_qT : g_kT) + (size_t)b * L_ * C_;
#pragma unroll
        for (int mt = 0; mt < 4; mt++) {
            int o = o0 + wr * 64 + mt * 16 + r;
            float bo = bias[o], bo8 = bias[o + 8];
#pragma unroll
            for (int nt = 0; nt < 4; nt++) {
                int l = l0 + wc * 32 + nt * 8 + 2 * c;
                oT[(size_t)l * C_ + o]           = __float2bfloat16_rn(acc[mt][nt][0] + bo);
                oT[(size_t)(l + 1) * C_ + o]     = __float2bfloat16_rn(acc[mt][nt][1] + bo);
                oT[(size_t)l * C_ + o + 8]       = __float2bfloat16_rn(acc[mt][nt][2] + bo8);
                oT[(size_t)(l + 1) * C_ + o + 8] = __float2bfloat16_rn(acc[mt][nt][3] + bo8);
            }
        }
    } else {
        __nv_bfloat16* ov = g_v + (size_t)b * C_ * L_;
#pragma unroll
        for (int mt = 0; mt < 4; mt++) {
            int o = o0 + wr * 64 + mt * 16 + r;
            float bo = bias[o], bo8 = bias[o + 8];
#pragma unroll
            for (int nt = 0; nt < 4; nt++) {
                int l = l0 + wc * 32 + nt * 8 + 2 * c;
                *(__nv_bfloat162*)(ov + (size_t)o * L_ + l) =
                    __floats2bfloat162_rn(acc[mt][nt][0] + bo, acc[mt][nt][1] + bo);
                *(__nv_bfloat162*)(ov + (size_t)(o + 8) * L_ + l) =
                    __floats2bfloat162_rn(acc[mt][nt][2] + bo8, acc[mt][nt][3] + bo8);
            }
        }
    }
}

// ---------------------------------------------------------------------------
// Launch
// ---------------------------------------------------------------------------
extern "C" void kernel_launch(void* const* d_in, const int* in_sizes, int n_in,
                              void* d_out, int out_size)
{
    (void)in_sizes; (void)n_in; (void)out_size;
    const float* x  = (const float*)d_in[0];
    const float* Wq = (const float*)d_in[1];
    const float* bq = (const float*)d_in[2];
    const float* Wk = (const float*)d_in[3];
    const float* bk = (const float*)d_in[4];
    const float* Wv = (const float*)d_in[5];
    const float* bv = (const float*)d_in[6];
    float* out = (float*)d_out;

    cudaFuncSetAttribute((const void*)qkv16_kernel,
                         cudaFuncAttributeMaxDynamicSharedMemorySize, SMEM_DYN);
    cudaFuncSetAttribute((const void*)flash_kernel,
                         cudaFuncAttributeMaxDynamicSharedMemorySize, FT_SMEM);

    dim3 gx(L_ / 128, C_ / 32, B_ + 1);     // (16, 8, 9): z==8 does W convert
    conv_kernel<<<gx, dim3(32, 8)>>>(x, Wq, Wk, Wv);

    dim3 gq(L_ / 128, C_ / 128, B_ * 3);    // (16, 2, 24)
    qkv16_kernel<<<gq, NTHR, SMEM_DYN>>>(bq, bk, bv);

    dim3 gf(L_ / 128, B_);                  // (16, 8) = 128 CTAs
    flash_kernel<<<gf, FT_NTHR, FT_SMEM>>>(x, out);
}

// round 17
// speedup vs baseline: 1.2413x; 1.0109x over previous
#include <cuda_runtime.h>
#include <cuda_bf16.h>
#include <cstdint>

#define B_  8
#define C_  256
#define L_  2048

// ---------------------------------------------------------------------------
// Scratch (no cudaMalloc allowed)
// ---------------------------------------------------------------------------
__device__ __align__(16) __nv_bfloat16 g_xT[B_ * L_ * C_];   // [B,L,C]
__device__ __align__(16) __nv_bfloat16 g_Wb[3 * C_ * C_];    // q,k,v weights
__device__ __align__(16) __nv_bfloat16 g_qT[B_ * L_ * C_];   // [B,L,C]
__device__ __align__(16) __nv_bfloat16 g_kT[B_ * L_ * C_];   // [B,L,C]
__device__ __align__(16) __nv_bfloat16 g_v [B_ * C_ * L_];   // [B,C,L]

// ---------------------------------------------------------------------------
// common helpers
// ---------------------------------------------------------------------------
__device__ __forceinline__ uint32_t smem_u32(const void* p) {
    uint32_t a;
    asm("{ .reg .u64 t; cvta.to.shared.u64 t, %1; cvt.u32.u64 %0, t; }" : "=r"(a) : "l"(p));
    return a;
}
#define CP16(dst, src) \
    asm volatile("cp.async.cg.shared.global [%0], [%1], 16;" :: "r"(dst), "l"(src))
#define CP_COMMIT() asm volatile("cp.async.commit_group;" ::: "memory")
#define CP_WAIT0()  asm volatile("cp.async.wait_group 0;" ::: "memory")
#define CP_WAIT1()  asm volatile("cp.async.wait_group 1;" ::: "memory")
#define CP_WAIT2()  asm volatile("cp.async.wait_group 2;" ::: "memory")
#define CP_WAIT3()  asm volatile("cp.async.wait_group 3;" ::: "memory")
#define CP_WAIT4()  asm volatile("cp.async.wait_group 4;" ::: "memory")

__device__ __forceinline__ void mma_bf16(float acc[4], const uint32_t a[4],
                                         const uint32_t b[2]) {
    asm volatile(
        "mma.sync.aligned.m16n8k16.row.col.f32.bf16.bf16.f32 "
        "{%0,%1,%2,%3}, {%4,%5,%6,%7}, {%8,%9}, {%0,%1,%2,%3};"
        : "+f"(acc[0]), "+f"(acc[1]), "+f"(acc[2]), "+f"(acc[3])
        : "r"(a[0]), "r"(a[1]), "r"(a[2]), "r"(a[3]), "r"(b[0]), "r"(b[1]));
}
__device__ __forceinline__ void ldsm_x4(uint32_t addr, uint32_t r[4]) {
    asm volatile("ldmatrix.sync.aligned.m8n8.x4.shared.b16 {%0,%1,%2,%3}, [%4];"
        : "=r"(r[0]), "=r"(r[1]), "=r"(r[2]), "=r"(r[3]) : "r"(addr));
}

extern __shared__ __align__(16) char dynsmem[];

// ===========================================================================
//  FUSED ATTENTION — register-resident P, 4-buffer K ring, 2 syncs/tile.
//  grid (L/128, B), 256 threads = 8 warps. Warp: 16 rows x 128 keys (S),
//  16 rows x 256 ch (O). Fragment lookahead depth 2 (ring of 3).
// ===========================================================================
#define FT_NTHR 256
#define QROW 528                       // 256 bf16 + 16B pad
#define KROW 144                       // 64 bf16 + 16B pad
#define VROW 144
#define OFF_Q   0                      // 128 x 528   = 67584
#define OFF_K   67584                  // 4 x 128x144 = 73728
#define KBUFSZ  18432
#define OFF_V   141312                 // 2 x 256x144 = 73728
#define VBUFSZ  36864
#define FT_SMEM 215040
#define OROW 132                       // fp32 stage: 128 rows + 4 pad

__device__ __forceinline__ void ft_load_Q(const __nv_bfloat16* q, int tid, uint32_t sb) {
#pragma unroll
    for (int it = 0; it < 16; it++) {
        int s = tid + it * FT_NTHR;       // 0..4095
        int row = s >> 5, u = s & 31;
        CP16(sb + OFF_Q + row * QROW + u * 16, q + (size_t)row * C_ + u * 8);
    }
}
__device__ __forceinline__ void ft_load_K(const __nv_bfloat16* k, int key0, int cchunk,
                                          int tid, uint32_t sb) {
#pragma unroll
    for (int it = 0; it < 4; it++) {
        int s = tid + it * FT_NTHR;       // 0..1023
        int row = s >> 3, u = s & 7;
        CP16(sb + OFF_K + cchunk * KBUFSZ + row * KROW + u * 16,
             k + (size_t)(key0 + row) * C_ + cchunk * 64 + u * 8);
    }
}
// half h of the V tile: keys [key0 + h*64, +64), all 256 channels
__device__ __forceinline__ void ft_load_V(const __nv_bfloat16* v, int key0, int h,
                                          int tid, uint32_t sb) {
#pragma unroll
    for (int it = 0; it < 8; it++) {
        int s = tid + it * FT_NTHR;       // 0..2047
        int row = s >> 3, u = s & 7;      // row = channel
        CP16(sb + OFF_V + h * VBUFSZ + row * VROW + u * 16,
             v + (size_t)row * L_ + key0 + h * 64 + u * 8);
    }
}

__global__ __launch_bounds__(FT_NTHR, 1)
void flash_kernel(const float* __restrict__ x, float* __restrict__ out)
{
    const int tid = threadIdx.x, wid = tid >> 5, lane = tid & 31;
    const int l0 = blockIdx.x * 128, b = blockIdx.y;
    const uint32_t sb = smem_u32(dynsmem);

    const __nv_bfloat16* qg = g_qT + (size_t)b * L_ * C_ + (size_t)l0 * C_;
    const __nv_bfloat16* kg = g_kT + (size_t)b * L_ * C_;
    const __nv_bfloat16* vg = g_v + (size_t)b * C_ * L_;

    float acc_o[32][4];                  // 16 rows x 256 ch per warp
#pragma unroll
    for (int nt = 0; nt < 32; nt++)
#pragma unroll
        for (int j = 0; j < 4; j++) acc_o[nt][j] = 0.0f;
    float l_lo = 0.0f, l_hi = 0.0f;

    const uint32_t q_base = sb + OFF_Q
        + (uint32_t)(wid * 16 + (lane & 15)) * QROW + (lane >> 4) * 16;
    const uint32_t kb_off = (uint32_t)((lane & 7) + ((lane >> 4) & 1) * 8) * KROW
                            + ((lane >> 3) & 1) * 16;
    const uint32_t vb_off = (uint32_t)((lane & 7) + ((lane >> 4) & 1) * 8) * VROW
                            + ((lane >> 3) & 1) * 16;

    const float scale2 = 0.0625f * 1.4426950408889634f;  // 256^-0.5 * log2(e)

    // warmup: groups [Q],[c0],[c1]
    ft_load_Q(qg, tid, sb);            CP_COMMIT();
    ft_load_K(kg, 0, 0, tid, sb);      CP_COMMIT();
    ft_load_K(kg, 0, 1, tid, sb);      CP_COMMIT();

    for (int kt = 0; kt < 16; kt++) {
        const int key0 = kt * 128;

        float acc_s[16][4];
#pragma unroll
        for (int nt = 0; nt < 16; nt++)
#pragma unroll
            for (int j = 0; j < 4; j++) acc_s[nt][j] = 0.0f;

        // ---- S phase: chunk c lives in buffer c (no intra-tile reuse) ----
        // cc0: WAIT1 (c0 ready), SYNC (fences prev tile's V/K reads),
        //      then commit [c2],[c3],[V0],[V1].
        // cc1: WAIT4 (c1) | cc2: WAIT3 (c2) | cc3: WAIT2 (c3)   (no syncs)
#pragma unroll
        for (int cc = 0; cc < 4; cc++) {
            if (cc == 0) {
                CP_WAIT1();
                __syncthreads();
                ft_load_K(kg, key0, 2, tid, sb); CP_COMMIT();
                ft_load_K(kg, key0, 3, tid, sb); CP_COMMIT();
                ft_load_V(vg, key0, 0, tid, sb); CP_COMMIT();
                ft_load_V(vg, key0, 1, tid, sb); CP_COMMIT();
            }
            else if (cc == 1) { CP_WAIT4(); }
            else if (cc == 2) { CP_WAIT3(); }
            else              { CP_WAIT2(); }
            const uint32_t kbuf = sb + OFF_K + cc * KBUFSZ + kb_off;
#pragma unroll
            for (int ks = 0; ks < 4; ks++) {
                uint32_t a[4];
                ldsm_x4(q_base + cc * 128 + ks * 32, a);
                uint32_t bb[3][4];                       // lookahead depth 2
                ldsm_x4(kbuf + ks * 32, bb[0]);
                ldsm_x4(kbuf + (16 * KROW) + ks * 32, bb[1]);
#pragma unroll
                for (int np = 0; np < 8; np++) {
                    if (np < 6)
                        ldsm_x4(kbuf + (np + 2) * (16 * KROW) + ks * 32,
                                bb[(np + 2) % 3]);
                    mma_bf16(acc_s[2 * np],     a, &bb[np % 3][0]);
                    mma_bf16(acc_s[2 * np + 1], a, &bb[np % 3][2]);
                }
            }
        }

        // ---- O phase: exp2 + cvt (P in registers) fused with V MMAs ----
#pragma unroll
        for (int j = 0; j < 8; j++) {
            float p00 = exp2f(acc_s[2 * j][0] * scale2);
            float p01 = exp2f(acc_s[2 * j][1] * scale2);
            float p02 = exp2f(acc_s[2 * j][2] * scale2);
            float p03 = exp2f(acc_s[2 * j][3] * scale2);
            float p10 = exp2f(acc_s[2 * j + 1][0] * scale2);
            float p11 = exp2f(acc_s[2 * j + 1][1] * scale2);
            float p12 = exp2f(acc_s[2 * j + 1][2] * scale2);
            float p13 = exp2f(acc_s[2 * j + 1][3] * scale2);
            l_lo += p00 + p01 + p10 + p11;
            l_hi += p02 + p03 + p12 + p13;
            uint32_t a[4];
            *(__nv_bfloat162*)&a[0] = __floats2bfloat162_rn(p00, p01);
            *(__nv_bfloat162*)&a[1] = __floats2bfloat162_rn(p02, p03);
            *(__nv_bfloat162*)&a[2] = __floats2bfloat162_rn(p10, p11);
            *(__nv_bfloat162*)&a[3] = __floats2bfloat162_rn(p12, p13);

            if (j == 0) {
                CP_WAIT1();                    // V0 complete (V1 newest pending)
                __syncthreads();               // fences S-phase K reads
                if (kt + 1 < 16) {             // next tile's c0/c1 into bufs 0/1
                    ft_load_K(kg, key0 + 128, 0, tid, sb); CP_COMMIT();
                    ft_load_K(kg, key0 + 128, 1, tid, sb); CP_COMMIT();
                }
            } else if (j == 4) {
                if (kt + 1 < 16) { CP_WAIT2(); } else { CP_WAIT0(); }  // V1 done
            }

            const uint32_t vb = sb + OFF_V + (j >> 2) * VBUFSZ + vb_off + (j & 3) * 32;
            uint32_t bb[3][4];                           // lookahead depth 2
            ldsm_x4(vb, bb[0]);
            ldsm_x4(vb + (16 * VROW), bb[1]);
#pragma unroll
            for (int np = 0; np < 16; np++) {
                if (np < 14)
                    ldsm_x4(vb + (np + 2) * (16 * VROW), bb[(np + 2) % 3]);
                mma_bf16(acc_o[2 * np],     a, &bb[np % 3][0]);
                mma_bf16(acc_o[2 * np + 1], a, &bb[np % 3][2]);
            }
        }
        // next tile's cc0 sync fences this tile's V reads before V rewrites
    }

    // ---- epilogue: stage normalized O in smem [ch][row], coalesced out ----
    const int g = lane >> 2, tc = lane & 3;
    l_lo += __shfl_xor_sync(~0u, l_lo, 1);
    l_lo += __shfl_xor_sync(~0u, l_lo, 2);
    l_hi += __shfl_xor_sync(~0u, l_hi, 1);
    l_hi += __shfl_xor_sync(~0u, l_hi, 2);
    const float inv_lo = 1.0f / l_lo;
    const float inv_hi = 1.0f / l_hi;

    __syncthreads();   // all K/V/Q smem uses done; reuse as fp32 stage
    float* smemf = (float*)dynsmem;    // [256 ch][OROW]; 135168 B <= FT_SMEM
    const int rlo_l = wid * 16 + g;    // block-local rows
    const int rhi_l = rlo_l + 8;
#pragma unroll
    for (int nt = 0; nt < 32; nt++) {
        const int ch = nt * 8 + 2 * tc;
        smemf[ch * OROW + rlo_l]       = acc_o[nt][0] * inv_lo;
        smemf[(ch + 1) * OROW + rlo_l] = acc_o[nt][1] * inv_lo;
        smemf[ch * OROW + rhi_l]       = acc_o[nt][2] * inv_hi;
        smemf[(ch + 1) * OROW + rhi_l] = acc_o[nt][3] * inv_hi;
    }
    __syncthreads();

    const float* xb = x + (size_t)b * C_ * L_;
    float* ob = out + (size_t)b * C_ * L_;
    // 256 ch x 128 rows = 8192 float4, 32 per thread, fully coalesced
#pragma unroll
    for (int it = 0; it < 32; it++) {
        int gid = tid + it * FT_NTHR;     // 0..8191
        int ch = gid >> 5;                // 32 float4 per channel row
        int seg = gid & 31;
        size_t go = (size_t)ch * L_ + l0 + seg * 4;
        float4 xv = *(const float4*)(xb + go);
        const float* sp = smemf + ch * OROW + seg * 4;
        float4 o;
        o.x = sp[0] + xv.x;
        o.y = sp[1] + xv.y;
        o.z = sp[2] + xv.z;
        o.w = sp[3] + xv.w;
        *(float4*)(ob + go) = o;
    }
}

// ===========================================================================
//  QKV projection (unchanged, 256 threads, 2x4 warps)
// ===========================================================================
#define NTHR 256
#define ROWB 144
#define TILE_B (128 * ROWB)
#define STAGE  (2 * TILE_B)
#define NSTAGE 3
#define SMEM_DYN (NSTAGE * STAGE)

__device__ __forceinline__ void load_pair(int slot,
                                          const __nv_bfloat16* __restrict__ A, int lda,
                                          const __nv_bfloat16* __restrict__ Bt, int ldb,
                                          int tid, uint32_t sb) {
    const uint32_t base = sb + slot * STAGE;
#pragma unroll
    for (int it = 0; it < 4; it++) {
        int s = tid + it * NTHR;
        int row = s >> 3;
        int c4 = s & 7;
        CP16(base + row * ROWB + c4 * 16, A + (size_t)row * lda + c4 * 8);
        CP16(base + TILE_B + row * ROWB + c4 * 16, Bt + (size_t)row * ldb + c4 * 8);
    }
}

__device__ __forceinline__ void mma_chunk16(uint32_t As, uint32_t Bs,
                                            int wr, int wc, int lane,
                                            float acc[4][4][4]) {
    const uint32_t aoff = (uint32_t)(wr * 64 + (lane & 15)) * ROWB + (lane >> 4) * 16;
    const uint32_t boff = (uint32_t)(wc * 32 + (lane & 7) + ((lane >> 4) & 1) * 8) * ROWB
                          + ((lane >> 3) & 1) * 16;
#pragma unroll
    for (int ks = 0; ks < 4; ks++) {
        uint32_t a[4][4], b[2][4];
#pragma unroll
        for (int mt = 0; mt < 4; mt++)
            ldsm_x4(As + aoff + mt * (16 * ROWB) + ks * 32, a[mt]);
#pragma unroll
        for (int np = 0; np < 2; np++)
            ldsm_x4(Bs + boff + np * (16 * ROWB) + ks * 32, b[np]);
#pragma unroll
        for (int mt = 0; mt < 4; mt++)
#pragma unroll
            for (int nt = 0; nt < 4; nt++)
                mma_bf16(acc[mt][nt], a[mt], &b[nt >> 1][(nt & 1) * 2]);
    }
}

__device__ __forceinline__ void gemm128(const __nv_bfloat16* __restrict__ Ag, int lda,
                                        const __nv_bfloat16* __restrict__ Bg, int ldb,
                                        int KC, float acc[4][4][4]) {
    const int tid = threadIdx.x;
    const int wid = tid >> 5, lane = tid & 31;
    const int wr = wid >> 2, wc = wid & 3;
    const uint32_t sb = smem_u32(dynsmem);

    load_pair(0, Ag, lda, Bg, ldb, tid, sb);
    CP_COMMIT();
    load_pair(1, Ag + 64, lda, Bg + 64, ldb, tid, sb);
    CP_COMMIT();

    for (int kb = 0; kb < KC; kb++) {
        if (kb + 1 < KC) { CP_WAIT1(); } else { CP_WAIT0(); }
        __syncthreads();
        if (kb + 2 < KC) {
            load_pair((kb + 2) % NSTAGE, Ag + (size_t)(kb + 2) * 64, lda,
                      Bg + (size_t)(kb + 2) * 64, ldb, tid, sb);
            CP_COMMIT();
        }
        const uint32_t As = sb + (kb % NSTAGE) * STAGE;
        mma_chunk16(As, As + TILE_B, wr, wc, lane, acc);
        __syncthreads();
    }
}

#define ACC_INIT(acc) \
    do { \
        _Pragma("unroll") for (int i = 0; i < 4; i++) \
        _Pragma("unroll") for (int j = 0; j < 4; j++) \
        _Pragma("unroll") for (int q = 0; q < 4; q++) acc[i][j][q] = 0.0f; \
    } while (0)

// ---------------------------------------------------------------------------
// conv v2: z<8 -> xT transpose+convert; z==8 -> W convert.
// grid (16, 8, 9), block (32, 8)
// ---------------------------------------------------------------------------
__global__ void conv_kernel(const float* __restrict__ x,
                            const float* __restrict__ Wq,
                            const float* __restrict__ Wk,
                            const float* __restrict__ Wv) {
    const int tx = threadIdx.x, ty = threadIdx.y;
    const int tid = ty * 32 + tx;
    if (blockIdx.z == 8) {
        int gid = (blockIdx.y * 16 + blockIdx.x) * 256 + tid;   // 0..32767
#pragma unroll
        for (int r = 0; r < 2; r++) {
            int f = gid + r * 32768;
            if (f < 49152) {
                int p = f >> 14;
                int off = (f & 16383) * 4;
                const float* W = (p == 0) ? Wq : (p == 1) ? Wk : Wv;
                float4 w = *(const float4*)(W + off);
                __nv_bfloat16* o = g_Wb + p * C_ * C_ + off;
                *(__nv_bfloat162*)(o)     = __floats2bfloat162_rn(w.x, w.y);
                *(__nv_bfloat162*)(o + 2) = __floats2bfloat162_rn(w.z, w.w);
            }
        }
        return;
    }
    __shared__ float t[32][133];
    const int b = blockIdx.z, l0 = blockIdx.x * 128, c0 = blockIdx.y * 32;
    const float* xb = x + (size_t)b * C_ * L_;
#pragma unroll
    for (int i = ty; i < 32; i += 8) {
        float4 v = *(const float4*)(xb + (size_t)(c0 + i) * L_ + l0 + tx * 4);
        t[i][tx * 4 + 0] = v.x;
        t[i][tx * 4 + 1] = v.y;
        t[i][tx * 4 + 2] = v.z;
        t[i][tx * 4 + 3] = v.w;
    }
    __syncthreads();
    __nv_bfloat16* o = g_xT + (size_t)b * L_ * C_;
#pragma unroll
    for (int it = 0; it < 16; it++) {
        int j = it * 8 + ty;
        o[(size_t)(l0 + j) * C_ + c0 + tx] = __float2bfloat16_rn(t[tx][j]);
    }
}

__global__ __launch_bounds__(NTHR)
void qkv16_kernel(const float* __restrict__ bq,
                  const float* __restrict__ bk,
                  const float* __restrict__ bv)
{
    const int tid = threadIdx.x, wid = tid >> 5, lane = tid & 31;
    const int wr = wid >> 2, wc = wid & 3;
    const int z = blockIdx.z, b = z / 3, p = z - b * 3;
    const int l0 = blockIdx.x * 128, o0 = blockIdx.y * 128;
    const float* bias = (p == 0) ? bq : (p == 1) ? bk : bv;

    const __nv_bfloat16* Ag = g_Wb + p * C_ * C_ + (size_t)o0 * C_;
    const __nv_bfloat16* Bg = g_xT + (size_t)b * L_ * C_ + (size_t)l0 * C_;

    float acc[4][4][4];
    ACC_INIT(acc);
    gemm128(Ag, C_, Bg, C_, C_ / 64, acc);

    const int r = lane >> 2, c = lane & 3;
    if (p < 2) {
        __nv_bfloat16* oT = (p == 0 ? g_qT : g_kT) + (size_t)b * L_ * C_;
#pragma unroll
        for (int mt = 0; mt < 4; mt++) {
            int o = o0 + wr * 64 + mt * 16 + r;
            float bo = bias[o], bo8 = bias[o + 8];
#pragma unroll
            for (int nt = 0; nt < 4; nt++) {
                int l = l0 + wc * 32 + nt * 8 + 2 * c;
                oT[(size_t)l * C_ + o]           = __float2bfloat16_rn(acc[mt][nt][0] + bo);
                oT[(size_t)(l + 1) * C_ + o]     = __float2bfloat16_rn(acc[mt][nt][1] + bo);
                oT[(size_t)l * C_ + o + 8]       = __float2bfloat16_rn(acc[mt][nt][2] + bo8);
                oT[(size_t)(l + 1) * C_ + o + 8] = __float2bfloat16_rn(acc[mt][nt][3] + bo8);
            }
        }
    } else {
        __nv_bfloat16* ov = g_v + (size_t)b * C_ * L_;
#pragma unroll
        for (int mt = 0; mt < 4; mt++) {
            int o = o0 + wr * 64 + mt * 16 + r;
            float bo = bias[o], bo8 = bias[o + 8];
#pragma unroll
            for (int nt = 0; nt < 4; nt++) {
                int l = l0 + wc * 32 + nt * 8 + 2 * c;
                *(__nv_bfloat162*)(ov + (size_t)o * L_ + l) =
                    __floats2bfloat162_rn(acc[mt][nt][0] + bo, acc[mt][nt][1] + bo);
                *(__nv_bfloat162*)(ov + (size_t)(o + 8) * L_ + l) =
                    __floats2bfloat162_rn(acc[mt][nt][2] + bo8, acc[mt][nt][3] + bo8);
            }
        }
    }
}

// ---------------------------------------------------------------------------
// Launch
// ---------------------------------------------------------------------------
extern "C" void kernel_launch(void* const* d_in, const int* in_sizes, int n_in,
                              void* d_out, int out_size)
{
    (void)in_sizes; (void)n_in; (void)out_size;
    const float* x  = (const float*)d_in[0];
    const float* Wq = (const float*)d_in[1];
    const float* bq = (const float*)d_in[2];
    const float* Wk = (const float*)d_in[3];
    const float* bk = (const float*)d_in[4];
    const float* Wv = (const float*)d_in[5];
    const float* bv = (const float*)d_in[6];
    float* out = (float*)d_out;

    cudaFuncSetAttribute((const void*)qkv16_kernel,
                         cudaFuncAttributeMaxDynamicSharedMemorySize, SMEM_DYN);
    cudaFuncSetAttribute((const void*)flash_kernel,
                         cudaFuncAttributeMaxDynamicSharedMemorySize, FT_SMEM);

    dim3 gx(L_ / 128, C_ / 32, B_ + 1);     // (16, 8, 9): z==8 does W convert
    conv_kernel<<<gx, dim3(32, 8)>>>(x, Wq, Wk, Wv);

    dim3 gq(L_ / 128, C_ / 128, B_ * 3);    // (16, 2, 24)
    qkv16_kernel<<<gq, NTHR, SMEM_DYN>>>(bq, bk, bv);

    dim3 gf(L_ / 128, B_);                  // (16, 8) = 128 CTAs
    flash_kernel<<<gf, FT_NTHR, FT_SMEM>>>(x, out);
}